// round 1
// baseline (speedup 1.0000x reference)
#include <cuda_runtime.h>
#include <cstdint>

#define NB 12
#define DM 128
#define NH 2
#define HD 64

struct Consts {
    float ta[NH];            // alpha' (scaled by log2e/sqrt(hd))
    float tb[NH][NB];        // beta'
    float gam[NH][NB];       // gamma'
    float del[NH][NB][NB];   // delta'
    float u[NH];             // va_h . Wo_h (unscaled)
    float w[NH][NB];         // vc[k,h] . Wo_h (unscaled)
    float bo;
};

__device__ Consts g_c;
__device__ float g_av[3][DM];          // qa, ka, va
__device__ float g_cv[3][NB][DM];      // qc[b], kc[b], vc[b]

__device__ __forceinline__ float ex2f(float v) {
    float y;
    asm("ex2.approx.f32 %0, %1;" : "=f"(y) : "f"(v));
    return y;
}

// ---------------------------------------------------------------------------
// Setup 1: project w_embed and (b_embed + band_pos[b]) through Wq/Wk/Wv.
// 3 mats * 13 vectors * 128 components = 4992 length-128 dot products.
// ---------------------------------------------------------------------------
__global__ void spec_setup1(const float* __restrict__ we, const float* __restrict__ be,
                            const float* __restrict__ bp,
                            const float* __restrict__ Wq, const float* __restrict__ bq,
                            const float* __restrict__ Wk, const float* __restrict__ bk,
                            const float* __restrict__ Wv, const float* __restrict__ bv) {
    int id = blockIdx.x * blockDim.x + threadIdx.x;
    if (id >= 3 * 13 * DM) return;
    int m = id / (13 * DM);
    int r = id % (13 * DM);
    int v = r / DM;       // 0 = 'a' vector, 1..12 = band vector
    int i = r % DM;
    const float* W  = (m == 0) ? Wq : (m == 1) ? Wk : Wv;
    const float* bb = (m == 0) ? bq : (m == 1) ? bk : bv;
    const float* row = W + i * DM;
    float acc = 0.f;
    if (v == 0) {
        #pragma unroll 8
        for (int d = 0; d < DM; d++) acc = fmaf(row[d], we[d], acc);
        g_av[m][i] = acc;
    } else {
        const float* bpd = bp + (v - 1) * DM;
        #pragma unroll 8
        for (int d = 0; d < DM; d++) acc = fmaf(row[d], be[d] + bpd[d], acc);
        g_cv[m][v - 1][i] = acc + bb[i];
    }
}

// ---------------------------------------------------------------------------
// Setup 2: reduce projected vectors to the scalar attention constants.
// One block per head, one thread per length-64 dot product.
// ---------------------------------------------------------------------------
__global__ void spec_setup2(const float* __restrict__ Wo, const float* __restrict__ bo) {
    int h = blockIdx.x;
    int t = threadIdx.x;
    const float cfac = 0.125f * 1.4426950408889634f;  // (1/sqrt(64)) * log2(e)
    int off = h * HD;
    const float* qa = &g_av[0][off];
    const float* ka = &g_av[1][off];
    const float* va = &g_av[2][off];
    const float* wo = Wo + off;

    auto dot64 = [](const float* a, const float* b) {
        float s = 0.f;
        #pragma unroll 8
        for (int j = 0; j < HD; j++) s = fmaf(a[j], b[j], s);
        return s;
    };

    if (t == 0)       g_c.ta[h] = dot64(qa, ka) * cfac;
    else if (t == 1)  g_c.u[h]  = dot64(va, wo);
    else if (t < 14)  { int b = t - 2;  g_c.tb[h][b]  = dot64(qa, &g_cv[1][b][off]) * cfac; }
    else if (t < 26)  { int b = t - 14; g_c.gam[h][b] = dot64(&g_cv[0][b][off], ka) * cfac; }
    else if (t < 38)  { int b = t - 26; g_c.w[h][b]   = dot64(&g_cv[2][b][off], wo); }
    else if (t < 182) {
        int idx = t - 38, q = idx / NB, k = idx % NB;
        g_c.del[h][q][k] = dot64(&g_cv[0][q][off], &g_cv[1][k][off]) * cfac;
    } else if (t == 182 && h == 0) {
        g_c.bo = bo[0];
    }
}

// ---------------------------------------------------------------------------
// Main kernel: one thread per token. Scalarized attention.
//   s[q,k]  = x_q*t_k + x_k*gam_q + del_qk   (already in log2 domain, scaled)
//   e = 2^s ; P = e / rowsum ; delta_q += sum_k P * m_k ; m_k = u*x_k + w_k
// ---------------------------------------------------------------------------
__global__ __launch_bounds__(128) void spec_main(const float* __restrict__ x,
                                                 float* __restrict__ out, int N) {
    __shared__ Consts sC;
    {
        const float* src = (const float*)&g_c;
        float* dst = (float*)&sC;
        for (int i = threadIdx.x; i < (int)(sizeof(Consts) / 4); i += blockDim.x)
            dst[i] = src[i];
    }
    __syncthreads();

    int n = blockIdx.x * blockDim.x + threadIdx.x;
    if (n >= N) return;

    const float4* xp = (const float4*)(x + (size_t)n * NB);
    float4 a0 = xp[0], a1 = xp[1], a2 = xp[2];
    float xv[NB] = {a0.x, a0.y, a0.z, a0.w, a1.x, a1.y, a1.z, a1.w,
                    a2.x, a2.y, a2.z, a2.w};

    float delta[NB];
    #pragma unroll
    for (int q = 0; q < NB; q++) delta[q] = sC.bo;

    #pragma unroll
    for (int h = 0; h < NH; h++) {
        float t[NB], m[NB];
        float ah = sC.ta[h], uh = sC.u[h];
        #pragma unroll
        for (int k = 0; k < NB; k++) {
            t[k] = fmaf(xv[k], ah, sC.tb[h][k]);
            m[k] = fmaf(xv[k], uh, sC.w[h][k]);
        }
        #pragma unroll
        for (int q = 0; q < NB; q++) {
            float gq = sC.gam[h][q];
            float rs = 0.f, ds = 0.f;
            #pragma unroll
            for (int k = 0; k < NB; k++) {
                float s = fmaf(xv[q], t[k], fmaf(xv[k], gq, sC.del[h][q][k]));
                float e = ex2f(s);
                rs += e;
                ds = fmaf(e, m[k], ds);
            }
            delta[q] += __fdividef(ds, rs);
        }
    }

    float4 o0 = make_float4(xv[0] + delta[0], xv[1] + delta[1], xv[2] + delta[2], xv[3] + delta[3]);
    float4 o1 = make_float4(xv[4] + delta[4], xv[5] + delta[5], xv[6] + delta[6], xv[7] + delta[7]);
    float4 o2 = make_float4(xv[8] + delta[8], xv[9] + delta[9], xv[10] + delta[10], xv[11] + delta[11]);
    float4* op = (float4*)(out + (size_t)n * NB);
    op[0] = o0; op[1] = o1; op[2] = o2;
}

// ---------------------------------------------------------------------------
// kernel_launch
// Inputs (metadata order): x, w_embed, b_embed, band_pos, Wq, bq, Wk, bk,
//                          Wv, bv, Wo, bo
// ---------------------------------------------------------------------------
extern "C" void kernel_launch(void* const* d_in, const int* in_sizes, int n_in,
                              void* d_out, int out_size) {
    const float* x  = (const float*)d_in[0];
    const float* we = (const float*)d_in[1];
    const float* be = (const float*)d_in[2];
    const float* bp = (const float*)d_in[3];
    const float* Wq = (const float*)d_in[4];
    const float* bq = (const float*)d_in[5];
    const float* Wk = (const float*)d_in[6];
    const float* bk = (const float*)d_in[7];
    const float* Wv = (const float*)d_in[8];
    const float* bv = (const float*)d_in[9];
    const float* Wo = (const float*)d_in[10];
    const float* bo = (const float*)d_in[11];
    float* out = (float*)d_out;

    int N = in_sizes[0] / NB;  // 65536 tokens

    int s1_threads = 3 * 13 * DM;  // 4992
    spec_setup1<<<(s1_threads + 127) / 128, 128>>>(we, be, bp, Wq, bq, Wk, bk, Wv, bv);
    spec_setup2<<<NH, 192>>>(Wo, bo);
    spec_main<<<(N + 127) / 128, 128>>>(x, out, N);
}

// round 2
// speedup vs baseline: 1.9384x; 1.9384x over previous
#include <cuda_runtime.h>
#include <cstdint>

#define NB 12
#define DM 128
#define NH 2
#define HD 64

struct Consts {
    float ta[NH];            // alpha' (scaled by log2e/sqrt(hd))
    float tb[NH][NB];        // beta'
    float gam[NH][NB];       // gamma'
    float del[NH][NB][NB];   // delta'
    float u[NH];             // va_h . Wo_h (unscaled)
    float w[NH][NB];         // vc[k,h] . Wo_h (unscaled)
    float bo;
};

__device__ Consts g_c;
__device__ float g_av[3][DM];          // qa, ka, va
__device__ float g_cv[3][NB][DM];      // qc[b], kc[b], vc[b]

__device__ __forceinline__ float ex2f(float v) {
    float y;
    asm("ex2.approx.f32 %0, %1;" : "=f"(y) : "f"(v));
    return y;
}

__device__ __forceinline__ float warp_sum(float v) {
    v += __shfl_xor_sync(0xffffffffu, v, 16);
    v += __shfl_xor_sync(0xffffffffu, v, 8);
    v += __shfl_xor_sync(0xffffffffu, v, 4);
    v += __shfl_xor_sync(0xffffffffu, v, 2);
    v += __shfl_xor_sync(0xffffffffu, v, 1);
    return v;
}

// ---------------------------------------------------------------------------
// Setup 1: one WARP per length-128 dot product (4992 warps total).
// Lane l handles elements [4l, 4l+4) via float4 (coalesced), then shfl-reduce.
// ---------------------------------------------------------------------------
__global__ __launch_bounds__(128) void spec_setup1(
        const float* __restrict__ we, const float* __restrict__ be,
        const float* __restrict__ bp,
        const float* __restrict__ Wq, const float* __restrict__ bq,
        const float* __restrict__ Wk, const float* __restrict__ bk,
        const float* __restrict__ Wv, const float* __restrict__ bv) {
    int gw = (blockIdx.x * blockDim.x + threadIdx.x) >> 5;
    int lane = threadIdx.x & 31;
    if (gw >= 3 * 13 * DM) return;
    int m = gw / (13 * DM);
    int r = gw % (13 * DM);
    int v = r / DM;       // 0 = 'a' vector, 1..12 = band vector
    int i = r % DM;
    const float* W  = (m == 0) ? Wq : (m == 1) ? Wk : Wv;
    const float* bb = (m == 0) ? bq : (m == 1) ? bk : bv;

    float4 rw = ((const float4*)(W + i * DM))[lane];
    float partial;
    if (v == 0) {
        float4 e = ((const float4*)we)[lane];
        partial = rw.x * e.x + rw.y * e.y + rw.z * e.z + rw.w * e.w;
    } else {
        float4 e  = ((const float4*)be)[lane];
        float4 p  = ((const float4*)(bp + (v - 1) * DM))[lane];
        partial = rw.x * (e.x + p.x) + rw.y * (e.y + p.y)
                + rw.z * (e.z + p.z) + rw.w * (e.w + p.w);
    }
    float s = warp_sum(partial);
    if (lane == 0) {
        if (v == 0) g_av[m][i] = s;
        else        g_cv[m][v - 1][i] = s + bb[i];
    }
}

// ---------------------------------------------------------------------------
// Setup 2: one WARP per length-64 dot product (365 warps).
// Lane l handles elements [2l, 2l+2) via float2, shfl-reduce.
// ---------------------------------------------------------------------------
__global__ __launch_bounds__(256) void spec_setup2(const float* __restrict__ Wo,
                                                   const float* __restrict__ bo) {
    int gw = (blockIdx.x * blockDim.x + threadIdx.x) >> 5;
    int lane = threadIdx.x & 31;
    const float cfac = 0.125f * 1.4426950408889634f;  // (1/sqrt(64)) * log2(e)

    if (gw >= NH * 182) {
        if (gw == NH * 182 && lane == 0) g_c.bo = bo[0];
        return;
    }
    int h = gw / 182;
    int t = gw % 182;
    int off = h * HD;

    const float* a;
    const float* b;
    float* dst;
    float sc = cfac;

    if (t == 0) {
        a = &g_av[0][off]; b = &g_av[1][off]; dst = &g_c.ta[h];
    } else if (t == 1) {
        a = &g_av[2][off]; b = Wo + off; dst = &g_c.u[h]; sc = 1.0f;
    } else if (t < 14) {
        int bd = t - 2;
        a = &g_av[0][off]; b = &g_cv[1][bd][off]; dst = &g_c.tb[h][bd];
    } else if (t < 26) {
        int bd = t - 14;
        a = &g_cv[0][bd][off]; b = &g_av[1][off]; dst = &g_c.gam[h][bd];
    } else if (t < 38) {
        int bd = t - 26;
        a = &g_cv[2][bd][off]; b = Wo + off; dst = &g_c.w[h][bd]; sc = 1.0f;
    } else {
        int idx = t - 38, q = idx / NB, k = idx % NB;
        a = &g_cv[0][q][off]; b = &g_cv[1][k][off]; dst = &g_c.del[h][q][k];
    }

    float2 av = ((const float2*)a)[lane];
    float2 bv = ((const float2*)b)[lane];
    float partial = av.x * bv.x + av.y * bv.y;
    float s = warp_sum(partial);
    if (lane == 0) *dst = s * sc;
}

// ---------------------------------------------------------------------------
// Main kernel: one thread per token. Scalarized attention.
//   s[q,k]  = x_q*t_k + x_k*gam_q + del_qk   (already in log2 domain, scaled)
//   e = 2^s ; P = e / rowsum ; delta_q += sum_k P * m_k ; m_k = u*x_k + w_k
// ---------------------------------------------------------------------------
__global__ __launch_bounds__(128) void spec_main(const float* __restrict__ x,
                                                 float* __restrict__ out, int N) {
    __shared__ Consts sC;
    {
        const float* src = (const float*)&g_c;
        float* dst = (float*)&sC;
        for (int i = threadIdx.x; i < (int)(sizeof(Consts) / 4); i += blockDim.x)
            dst[i] = src[i];
    }
    __syncthreads();

    int n = blockIdx.x * blockDim.x + threadIdx.x;
    if (n >= N) return;

    const float4* xp = (const float4*)(x + (size_t)n * NB);
    float4 a0 = xp[0], a1 = xp[1], a2 = xp[2];
    float xv[NB] = {a0.x, a0.y, a0.z, a0.w, a1.x, a1.y, a1.z, a1.w,
                    a2.x, a2.y, a2.z, a2.w};

    float delta[NB];
    #pragma unroll
    for (int q = 0; q < NB; q++) delta[q] = sC.bo;

    #pragma unroll
    for (int h = 0; h < NH; h++) {
        float t[NB], m[NB];
        float ah = sC.ta[h], uh = sC.u[h];
        #pragma unroll
        for (int k = 0; k < NB; k++) {
            t[k] = fmaf(xv[k], ah, sC.tb[h][k]);
            m[k] = fmaf(xv[k], uh, sC.w[h][k]);
        }
        #pragma unroll
        for (int q = 0; q < NB; q++) {
            float gq = sC.gam[h][q];
            float rs = 0.f, ds = 0.f;
            #pragma unroll
            for (int k = 0; k < NB; k++) {
                float s = fmaf(xv[q], t[k], fmaf(xv[k], gq, sC.del[h][q][k]));
                float e = ex2f(s);
                rs += e;
                ds = fmaf(e, m[k], ds);
            }
            delta[q] += __fdividef(ds, rs);
        }
    }

    float4 o0 = make_float4(xv[0] + delta[0], xv[1] + delta[1], xv[2] + delta[2], xv[3] + delta[3]);
    float4 o1 = make_float4(xv[4] + delta[4], xv[5] + delta[5], xv[6] + delta[6], xv[7] + delta[7]);
    float4 o2 = make_float4(xv[8] + delta[8], xv[9] + delta[9], xv[10] + delta[10], xv[11] + delta[11]);
    float4* op = (float4*)(out + (size_t)n * NB);
    op[0] = o0; op[1] = o1; op[2] = o2;
}

// ---------------------------------------------------------------------------
// kernel_launch
// Inputs (metadata order): x, w_embed, b_embed, band_pos, Wq, bq, Wk, bk,
//                          Wv, bv, Wo, bo
// ---------------------------------------------------------------------------
extern "C" void kernel_launch(void* const* d_in, const int* in_sizes, int n_in,
                              void* d_out, int out_size) {
    const float* x  = (const float*)d_in[0];
    const float* we = (const float*)d_in[1];
    const float* be = (const float*)d_in[2];
    const float* bp = (const float*)d_in[3];
    const float* Wq = (const float*)d_in[4];
    const float* bq = (const float*)d_in[5];
    const float* Wk = (const float*)d_in[6];
    const float* bk = (const float*)d_in[7];
    const float* Wv = (const float*)d_in[8];
    const float* bv = (const float*)d_in[9];
    const float* Wo = (const float*)d_in[10];
    const float* bo = (const float*)d_in[11];
    float* out = (float*)d_out;

    int N = in_sizes[0] / NB;  // 65536 tokens

    int s1_warps = 3 * 13 * DM;                 // 4992 warps, 4 per block
    spec_setup1<<<(s1_warps + 3) / 4, 128>>>(we, be, bp, Wq, bq, Wk, bk, Wv, bv);

    int s2_warps = NH * 182 + 1;                // 365 warps, 8 per block
    spec_setup2<<<(s2_warps + 7) / 8, 256>>>(Wo, bo);

    spec_main<<<(N + 127) / 128, 128>>>(x, out, N);
}